// round 11
// baseline (speedup 1.0000x reference)
#include <cuda_runtime.h>
#include <cuda_bf16.h>
#include <cstdint>

#define BB 64
#define SS 2048
#define DD 512
#define UU 512

// ---------------- scratch globals (no allocations allowed) ------------------
__device__ float g_bias[BB * UU];                  // dec@W2 + b1 + b2
__device__ float g_scores[BB * SS];                // pre-softmax scores
// enc converted: row r -> [hi k0..511 | lo k0..511] bf16  (256 MB)
__device__ __nv_bfloat16 g_encA[(size_t)BB * SS * 1024];
// W1 converted to [u][ hi k0..511 | lo k0..511 ]  (1 MB)
__device__ __nv_bfloat16 g_W1img[(size_t)UU * 1024];

// ---------------- helpers ----------------------------------------------------
__device__ __forceinline__ float tanh_fast(float x) {
    float e = __expf(2.0f * x);
    return 1.0f - __fdividef(2.0f, e + 1.0f);
}
__device__ __forceinline__ uint32_t smem_u32(const void* p) {
    uint32_t a;
    asm("{ .reg .u64 t; cvta.to.shared.u64 t, %1; cvt.u32.u64 %0, t; }"
        : "=r"(a) : "l"(p));
    return a;
}
__device__ __forceinline__ uint32_t pack2(__nv_bfloat16 a, __nv_bfloat16 b) {
    return ((uint32_t)__bfloat16_as_ushort(b) << 16) | __bfloat16_as_ushort(a);
}
#define CP16(dst, src) \
    asm volatile("cp.async.cg.shared.global [%0], [%1], 16;" \
                 :: "r"(dst), "l"(src) : "memory")
#define LDSM4(r0, r1, r2, r3, addr) \
    asm volatile("ldmatrix.sync.aligned.m8n8.x4.shared.b16 {%0,%1,%2,%3}, [%4];" \
                 : "=r"(r0), "=r"(r1), "=r"(r2), "=r"(r3) : "r"(addr))
#define MMA16816(d, a0, a1, a2, a3, b0, b1) \
    asm volatile( \
        "mma.sync.aligned.m16n8k16.row.col.f32.bf16.bf16.f32 " \
        "{%0,%1,%2,%3}, {%4,%5,%6,%7}, {%8,%9}, {%0,%1,%2,%3};" \
        : "+f"(d[0]), "+f"(d[1]), "+f"(d[2]), "+f"(d[3]) \
        : "r"(a0), "r"(a1), "r"(a2), "r"(a3), "r"(b0), "r"(b1))

// ---------------------------------------------------------------------------
// kernE: enc fp32 -> bf16 hi/lo image
// ---------------------------------------------------------------------------
__global__ __launch_bounds__(256) void kernE(const float* __restrict__ enc) {
    size_t lin = (size_t)blockIdx.x * 256 + threadIdx.x;
    size_t row = lin >> 7;
    int q = (int)(lin & 127);
    float4 f = *(const float4*)(enc + row * DD + q * 4);
    __nv_bfloat16 h0 = __float2bfloat16_rn(f.x), h1 = __float2bfloat16_rn(f.y);
    __nv_bfloat16 h2 = __float2bfloat16_rn(f.z), h3 = __float2bfloat16_rn(f.w);
    __nv_bfloat16 l0 = __float2bfloat16_rn(f.x - __bfloat162float(h0));
    __nv_bfloat16 l1 = __float2bfloat16_rn(f.y - __bfloat162float(h1));
    __nv_bfloat16 l2 = __float2bfloat16_rn(f.z - __bfloat162float(h2));
    __nv_bfloat16 l3 = __float2bfloat16_rn(f.w - __bfloat162float(h3));
    uint2 hv = {pack2(h0, h1), pack2(h2, h3)};
    uint2 lv = {pack2(l0, l1), pack2(l2, l3)};
    *(uint2*)(&g_encA[row * 1024 + q * 4]) = hv;
    *(uint2*)(&g_encA[row * 1024 + 512 + q * 4]) = lv;
}

// ---------------------------------------------------------------------------
// kernW: W1[k][u] -> g_W1img[u][hi k | lo k]; also zero g_scores
// ---------------------------------------------------------------------------
__global__ __launch_bounds__(256) void kernW(const float* __restrict__ W1) {
    int idx = blockIdx.x * 256 + threadIdx.x;
    int u = idx & 511, kg = idx >> 9;
    float x = W1[(size_t)kg * UU + u];
    __nv_bfloat16 h = __float2bfloat16_rn(x);
    __nv_bfloat16 l = __float2bfloat16_rn(x - __bfloat162float(h));
    g_W1img[(size_t)u * 1024 + kg] = h;
    g_W1img[(size_t)u * 1024 + 512 + kg] = l;
    if (idx < BB * SS) g_scores[idx] = 0.0f;
}

// ---------------------------------------------------------------------------
// kernA: g_bias[b,u] = dec@W2 + b1 + b2
// ---------------------------------------------------------------------------
__global__ __launch_bounds__(512) void kernA(const float* __restrict__ dec,
                                             const float* __restrict__ W2,
                                             const float* __restrict__ b1,
                                             const float* __restrict__ b2) {
    __shared__ float ds[DD];
    int b = blockIdx.x;
    for (int i = threadIdx.x; i < DD; i += blockDim.x) ds[i] = dec[b * DD + i];
    __syncthreads();
    int u = threadIdx.x;
    float acc = 0.0f;
#pragma unroll 8
    for (int k = 0; k < DD; k++) acc = fmaf(ds[k], W2[k * UU + u], acc);
    g_bias[b * UU + u] = acc + b1[u] + b2[u];
}

// ---------------------------------------------------------------------------
// kernB: bf16 mma.sync GEMM, tile M64 x N256 per CTA.
// 16 k32 super-tiles, each holding Ah/Al/Bh/Bl; 3 passes with fragment reuse
// (p0: Ah*Bh, p2: Al*Bh, p1: Ah*Bl). 2-stage ring, 2 CTAs/SM.
// Row stride 80 B (64 B data + 16 pad): 16B-aligned for cp.async,
// conflict-free for LDSM (20-word stride -> distinct bank groups).
// ---------------------------------------------------------------------------
#define APART 5120              // 64 rows * 80 B (one of hi/lo)
#define BPART 20480             // 256 rows * 80 B
#define ASLOT (2 * APART)       // 10240
#define SLOT  (ASLOT + 2 * BPART)   // 51200
#define EXTRA (2 * SLOT)        // 102400
#define SMEM_B_TOTAL (EXTRA + 1024 + 1024 + 1024)

__global__ __launch_bounds__(256, 2) void kernB(const float* __restrict__ Vp) {
    extern __shared__ char smraw[];
    const uint32_t smem = smem_u32(smraw);
    float* gBs = (float*)(smraw + EXTRA);
    float* Vs = (float*)(smraw + EXTRA + 1024);
    float* sPart = (float*)(smraw + EXTRA + 2048);

    const int tid = threadIdx.x;
    const int lane = tid & 31, w = tid >> 5;
    const int wm = w & 1, wn = w >> 1;          // warp tile 32(M) x 64(N)
    const int R = blockIdx.x * 64;
    const int b = blockIdx.x >> 5;
    const int s0 = (blockIdx.x & 31) * 64;
    const int N0 = blockIdx.y * 256;

    {
        gBs[tid] = g_bias[b * 512 + N0 + tid];
        Vs[tid] = Vp[N0 + tid];
    }

    // super-tile it (0..15): k0 = it*32; loads hi AND lo of A and B
    auto issue_tile = [&](int it, int slot) {
        int k0 = it * 32;
        const char* aSrc = (const char*)g_encA + (size_t)R * 2048 + k0 * 2;
        const char* bSrc = (const char*)g_W1img + (size_t)N0 * 2048 + k0 * 2;
        uint32_t aDst = smem + slot * SLOT;
        uint32_t bDst = aDst + ASLOT;
        // A: 512 chunks (2 parts x 64 rows x 4 chunks of 16B)
#pragma unroll
        for (int i = 0; i < 2; i++) {
            int id = tid + i * 256;
            int part = id >> 8, r = (id >> 2) & 63, c = id & 3;
            CP16(aDst + part * APART + r * 80 + c * 16,
                 aSrc + (size_t)r * 2048 + part * 1024 + c * 16);
        }
        // B: 2048 chunks (2 parts x 256 rows x 4)
#pragma unroll
        for (int i = 0; i < 8; i++) {
            int id = tid + i * 256;
            int part = id >> 10, r = (id >> 2) & 255, c = id & 3;
            CP16(bDst + part * BPART + r * 80 + c * 16,
                 bSrc + (size_t)r * 2048 + part * 1024 + c * 16);
        }
        asm volatile("cp.async.commit_group;" ::: "memory");
    };

    float acc[2][8][4];
#pragma unroll
    for (int mt = 0; mt < 2; mt++)
#pragma unroll
        for (int nt = 0; nt < 8; nt++)
#pragma unroll
            for (int j = 0; j < 4; j++) acc[mt][nt][j] = 0.0f;

    issue_tile(0, 0);

    const uint32_t aRowOff =
        (uint32_t)((wm * 32 + (lane & 15)) * 80 + ((lane >> 4) & 1) * 16);
    // B x4 (two 8-row n-tiles per load): row = wn*64 + (lane&7) + bit4*8
    const uint32_t bRowOff =
        (uint32_t)((wn * 64 + (lane & 7) + ((lane >> 4) & 1) * 8) * 80 +
                   ((lane >> 3) & 1) * 16);

    for (int it = 0; it < 16; it++) {
        asm volatile("cp.async.wait_group 0;" ::: "memory");
        __syncthreads();
        if (it + 1 < 16) issue_tile(it + 1, (it + 1) & 1);

        const uint32_t sbase = smem + (it & 1) * SLOT;
        const uint32_t sA = sbase + aRowOff;
        const uint32_t sB = sbase + ASLOT + bRowOff;
#pragma unroll
        for (int ks = 0; ks < 2; ks++) {
            // --- load Ah, Bh; pass0: Ah*Bh ---
            uint32_t ah[2][4];
#pragma unroll
            for (int mt = 0; mt < 2; mt++)
                LDSM4(ah[mt][0], ah[mt][1], ah[mt][2], ah[mt][3],
                      sA + mt * 16 * 80 + ks * 32);
            uint32_t bh[8][2];
#pragma unroll
            for (int ntp = 0; ntp < 4; ntp++)
                LDSM4(bh[ntp * 2][0], bh[ntp * 2][1],
                      bh[ntp * 2 + 1][0], bh[ntp * 2 + 1][1],
                      sB + ntp * 16 * 80 + ks * 32);
#pragma unroll
            for (int mt = 0; mt < 2; mt++)
#pragma unroll
                for (int nt = 0; nt < 8; nt++)
                    MMA16816(acc[mt][nt], ah[mt][0], ah[mt][1], ah[mt][2],
                             ah[mt][3], bh[nt][0], bh[nt][1]);
            // --- load Al; pass2: Al*Bh (Bh reused, then dead) ---
            {
                uint32_t al[2][4];
#pragma unroll
                for (int mt = 0; mt < 2; mt++)
                    LDSM4(al[mt][0], al[mt][1], al[mt][2], al[mt][3],
                          sA + APART + mt * 16 * 80 + ks * 32);
#pragma unroll
                for (int mt = 0; mt < 2; mt++)
#pragma unroll
                    for (int nt = 0; nt < 8; nt++)
                        MMA16816(acc[mt][nt], al[mt][0], al[mt][1], al[mt][2],
                                 al[mt][3], bh[nt][0], bh[nt][1]);
            }
            // --- load Bl; pass1: Ah*Bl (Ah reused) ---
            {
                uint32_t bl[8][2];
#pragma unroll
                for (int ntp = 0; ntp < 4; ntp++)
                    LDSM4(bl[ntp * 2][0], bl[ntp * 2][1],
                          bl[ntp * 2 + 1][0], bl[ntp * 2 + 1][1],
                          sB + BPART + ntp * 16 * 80 + ks * 32);
#pragma unroll
                for (int mt = 0; mt < 2; mt++)
#pragma unroll
                    for (int nt = 0; nt < 8; nt++)
                        MMA16816(acc[mt][nt], ah[mt][0], ah[mt][1], ah[mt][2],
                                 ah[mt][3], bl[nt][0], bl[nt][1]);
            }
        }
    }

    // ---- epilogue: bias + tanh + V-dot, reduce to per-row partials ----
    __syncthreads();
    const int t4 = lane & 3;
    float part[2][2];
#pragma unroll
    for (int mt = 0; mt < 2; mt++) { part[mt][0] = 0.f; part[mt][1] = 0.f; }
#pragma unroll
    for (int mt = 0; mt < 2; mt++)
#pragma unroll
        for (int nt = 0; nt < 8; nt++) {
            int n0 = wn * 64 + nt * 8 + 2 * t4;
            float v0 = Vs[n0], v1 = Vs[n0 + 1];
            float g0 = gBs[n0], g1 = gBs[n0 + 1];
            part[mt][0] += tanh_fast(acc[mt][nt][0] + g0) * v0 +
                           tanh_fast(acc[mt][nt][1] + g1) * v1;
            part[mt][1] += tanh_fast(acc[mt][nt][2] + g0) * v0 +
                           tanh_fast(acc[mt][nt][3] + g1) * v1;
        }
#pragma unroll
    for (int mt = 0; mt < 2; mt++)
#pragma unroll
        for (int rr = 0; rr < 2; rr++) {
            part[mt][rr] += __shfl_xor_sync(0xffffffffu, part[mt][rr], 1);
            part[mt][rr] += __shfl_xor_sync(0xffffffffu, part[mt][rr], 2);
        }
    if (t4 == 0) {
        int g = lane >> 2;
#pragma unroll
        for (int mt = 0; mt < 2; mt++)
#pragma unroll
            for (int rr = 0; rr < 2; rr++) {
                int row = wm * 32 + mt * 16 + rr * 8 + g;
                sPart[row * 4 + wn] = part[mt][rr];
            }
    }
    __syncthreads();
    if (tid < 64) {
        float s = sPart[tid * 4] + sPart[tid * 4 + 1] + sPart[tid * 4 + 2] +
                  sPart[tid * 4 + 3];
        atomicAdd(&g_scores[b * SS + s0 + tid], s);
    }
}

// ---------------------------------------------------------------------------
// kernC: softmax over S; writes attn; zeroes context region
// ---------------------------------------------------------------------------
__global__ __launch_bounds__(256) void kernC(float* __restrict__ out) {
    __shared__ float red[256];
    int b = blockIdx.x, tid = threadIdx.x;
    float v[8];
    float mx = -1e30f;
#pragma unroll
    for (int j = 0; j < 8; j++) {
        v[j] = g_scores[b * SS + tid + j * 256];
        mx = fmaxf(mx, v[j]);
    }
    red[tid] = mx;
    __syncthreads();
    for (int o = 128; o > 0; o >>= 1) {
        if (tid < o) red[tid] = fmaxf(red[tid], red[tid + o]);
        __syncthreads();
    }
    mx = red[0];
    __syncthreads();
    float s = 0.0f;
#pragma unroll
    for (int j = 0; j < 8; j++) {
        v[j] = __expf(v[j] - mx);
        s += v[j];
    }
    red[tid] = s;
    __syncthreads();
    for (int o = 128; o > 0; o >>= 1) {
        if (tid < o) red[tid] += red[tid + o];
        __syncthreads();
    }
    float inv = 1.0f / red[0];
#pragma unroll
    for (int j = 0; j < 8; j++)
        out[BB * UU + b * SS + tid + j * 256] = v[j] * inv;
    for (int i = tid; i < 512; i += 256) out[b * 512 + i] = 0.0f;
}

// ---------------------------------------------------------------------------
// kernD: context[b,d] = sum_s attn[b,s] * enc[b,s,d]
// ---------------------------------------------------------------------------
__global__ __launch_bounds__(512) void kernD(const float* __restrict__ enc,
                                             float* __restrict__ out) {
    __shared__ float as[128];
    int b = blockIdx.y, c = blockIdx.x, tid = threadIdx.x;
    if (tid < 128) as[tid] = out[BB * UU + b * SS + c * 128 + tid];
    __syncthreads();
    const float* e = enc + ((size_t)(b * SS + c * 128)) * DD + tid;
    float acc = 0.0f;
#pragma unroll 8
    for (int i = 0; i < 128; i++) acc = fmaf(as[i], e[(size_t)i * DD], acc);
    atomicAdd(&out[b * 512 + tid], acc);
}

// ---------------------------------------------------------------------------
extern "C" void kernel_launch(void* const* d_in, const int* in_sizes, int n_in,
                              void* d_out, int out_size) {
    const float* enc = (const float*)d_in[0];
    const float* dec = (const float*)d_in[1];
    const float* W1  = (const float*)d_in[2];
    const float* b1  = (const float*)d_in[3];
    const float* W2  = (const float*)d_in[4];
    const float* b2  = (const float*)d_in[5];
    const float* V   = (const float*)d_in[6];
    float* out = (float*)d_out;

    cudaFuncSetAttribute(kernB, cudaFuncAttributeMaxDynamicSharedMemorySize,
                         SMEM_B_TOTAL);

    kernE<<<65536, 256>>>(enc);
    kernW<<<1024, 256>>>(W1);
    kernA<<<BB, 512>>>(dec, W2, b1, b2);
    kernB<<<dim3(2048, 2), 256, SMEM_B_TOTAL>>>(V);
    kernC<<<BB, 256>>>(out);
    kernD<<<dim3(16, BB), 512>>>(enc, out);
}

// round 12
// speedup vs baseline: 1.4769x; 1.4769x over previous
#include <cuda_runtime.h>
#include <cuda_fp16.h>
#include <cstdint>

#define BB 64
#define SS 2048
#define DD 512
#define UU 512

// ---------------- scratch globals (no allocations allowed) ------------------
__device__ float g_bias[BB * UU];                  // dec@W2 + b1 + b2
__device__ float g_scores[BB * SS];                // pre-softmax scores
__device__ __half g_encH[(size_t)BB * SS * DD];    // enc as fp16 (128 MB)
__device__ __half g_W1h[(size_t)UU * DD];          // W1 as [u][k] fp16

// ---------------- helpers ----------------------------------------------------
__device__ __forceinline__ float tanh_fast(float x) {
    float e = __expf(2.0f * x);
    return 1.0f - __fdividef(2.0f, e + 1.0f);
}
__device__ __forceinline__ uint32_t smem_u32(const void* p) {
    uint32_t a;
    asm("{ .reg .u64 t; cvta.to.shared.u64 t, %1; cvt.u32.u64 %0, t; }"
        : "=r"(a) : "l"(p));
    return a;
}
#define CP16(dst, src) \
    asm volatile("cp.async.cg.shared.global [%0], [%1], 16;" \
                 :: "r"(dst), "l"(src) : "memory")
#define LDSM4(r0, r1, r2, r3, addr) \
    asm volatile("ldmatrix.sync.aligned.m8n8.x4.shared.b16 {%0,%1,%2,%3}, [%4];" \
                 : "=r"(r0), "=r"(r1), "=r"(r2), "=r"(r3) : "r"(addr))
#define MMAF16(d, a0, a1, a2, a3, b0, b1) \
    asm volatile( \
        "mma.sync.aligned.m16n8k16.row.col.f32.f16.f16.f32 " \
        "{%0,%1,%2,%3}, {%4,%5,%6,%7}, {%8,%9}, {%0,%1,%2,%3};" \
        : "+f"(d[0]), "+f"(d[1]), "+f"(d[2]), "+f"(d[3]) \
        : "r"(a0), "r"(a1), "r"(a2), "r"(a3), "r"(b0), "r"(b1))

// ---------------------------------------------------------------------------
// kernE: enc fp32 -> fp16 image
// ---------------------------------------------------------------------------
__global__ __launch_bounds__(256) void kernE(const float* __restrict__ enc) {
    size_t lin = (size_t)blockIdx.x * 256 + threadIdx.x;
    size_t row = lin >> 7;
    int q = (int)(lin & 127);
    float4 f = *(const float4*)(enc + row * DD + q * 4);
    __half2 p0 = __floats2half2_rn(f.x, f.y);
    __half2 p1 = __floats2half2_rn(f.z, f.w);
    uint2 v;
    v.x = *(uint32_t*)&p0;
    v.y = *(uint32_t*)&p1;
    *(uint2*)(&g_encH[row * DD + q * 4]) = v;
}

// ---------------------------------------------------------------------------
// kernW: W1[k][u] -> g_W1h[u][k] fp16; also zero g_scores
// ---------------------------------------------------------------------------
__global__ __launch_bounds__(256) void kernW(const float* __restrict__ W1) {
    int idx = blockIdx.x * 256 + threadIdx.x;   // 0..262143
    int u = idx & 511, kg = idx >> 9;
    g_W1h[(size_t)u * DD + kg] = __float2half_rn(W1[(size_t)kg * UU + u]);
    if (idx < BB * SS) g_scores[idx] = 0.0f;
}

// ---------------------------------------------------------------------------
// kernA: g_bias[b,u] = dec@W2 + b1 + b2
// ---------------------------------------------------------------------------
__global__ __launch_bounds__(512) void kernA(const float* __restrict__ dec,
                                             const float* __restrict__ W2,
                                             const float* __restrict__ b1,
                                             const float* __restrict__ b2) {
    __shared__ float ds[DD];
    int b = blockIdx.x;
    for (int i = threadIdx.x; i < DD; i += blockDim.x) ds[i] = dec[b * DD + i];
    __syncthreads();
    int u = threadIdx.x;
    float acc = 0.0f;
#pragma unroll 8
    for (int k = 0; k < DD; k++) acc = fmaf(ds[k], W2[k * UU + u], acc);
    g_bias[b * UU + u] = acc + b1[u] + b2[u];
}

// ---------------------------------------------------------------------------
// kernB: fp16 single-pass mma.sync GEMM, tile M64 x N256 per CTA, K=512.
// 8 k64 tiles, 2-stage cp.async ring, one __syncthreads per tile, 2 CTAs/SM.
// Row stride 144 B (128 B data + 16 pad).
// ---------------------------------------------------------------------------
#define ASLOT 9216              // 64 rows * 144 B
#define SLOT  46080             // A (9216) + B (36864)
#define EXTRA 92160             // 2 stages
#define SMEM_B_TOTAL (EXTRA + 1024 + 1024 + 1024)

__global__ __launch_bounds__(256, 2) void kernB(const float* __restrict__ Vp) {
    extern __shared__ char smraw[];
    const uint32_t smem = smem_u32(smraw);
    float* gBs = (float*)(smraw + EXTRA);
    float* Vs = (float*)(smraw + EXTRA + 1024);
    float* sPart = (float*)(smraw + EXTRA + 2048);

    const int tid = threadIdx.x;
    const int lane = tid & 31, w = tid >> 5;
    const int wm = w & 1, wn = w >> 1;          // warp tile 32(M) x 64(N)
    const int R = blockIdx.x * 64;
    const int b = blockIdx.x >> 5;
    const int s0 = (blockIdx.x & 31) * 64;
    const int N0 = blockIdx.y * 256;

    {
        gBs[tid] = g_bias[b * 512 + N0 + tid];
        Vs[tid] = Vp[N0 + tid];
    }

    // tile it (0..7): k0 = it*64 fp16 elements = it*128 bytes
    auto issue_tile = [&](int it, int slot) {
        const char* aSrc = (const char*)g_encH + (size_t)R * 1024 + it * 128;
        const char* bSrc = (const char*)g_W1h + (size_t)N0 * 1024 + it * 128;
        uint32_t aDst = smem + slot * SLOT;
        uint32_t bDst = aDst + ASLOT;
        // A: 512 chunks (64 rows x 8 chunks of 16B), 2/thread
#pragma unroll
        for (int i = 0; i < 2; i++) {
            int lin = tid + i * 256;
            int r = lin >> 3, c = lin & 7;
            CP16(aDst + r * 144 + c * 16, aSrc + (size_t)r * 1024 + c * 16);
        }
        // B: 2048 chunks (256 rows x 8), 8/thread
#pragma unroll
        for (int i = 0; i < 8; i++) {
            int lin = tid + i * 256;
            int r = lin >> 3, c = lin & 7;
            CP16(bDst + r * 144 + c * 16, bSrc + (size_t)r * 1024 + c * 16);
        }
        asm volatile("cp.async.commit_group;" ::: "memory");
    };

    float acc[2][8][4];
#pragma unroll
    for (int mt = 0; mt < 2; mt++)
#pragma unroll
        for (int nt = 0; nt < 8; nt++)
#pragma unroll
            for (int j = 0; j < 4; j++) acc[mt][nt][j] = 0.0f;

    issue_tile(0, 0);

    const uint32_t aRowOff =
        (uint32_t)((wm * 32 + (lane & 15)) * 144 + ((lane >> 4) & 1) * 16);
    // B x4 (two 8-row n-tiles per load): row = wn*64 + (lane&7) + bit4*8
    const uint32_t bRowOff =
        (uint32_t)((wn * 64 + (lane & 7) + ((lane >> 4) & 1) * 8) * 144 +
                   ((lane >> 3) & 1) * 16);

    for (int it = 0; it < 8; it++) {
        asm volatile("cp.async.wait_group 0;" ::: "memory");
        __syncthreads();
        if (it + 1 < 8) issue_tile(it + 1, (it + 1) & 1);

        const uint32_t sbase = smem + (it & 1) * SLOT;
        const uint32_t sA = sbase + aRowOff;
        const uint32_t sB = sbase + ASLOT + bRowOff;
#pragma unroll
        for (int ks = 0; ks < 4; ks++) {
            uint32_t a[2][4];
#pragma unroll
            for (int mt = 0; mt < 2; mt++)
                LDSM4(a[mt][0], a[mt][1], a[mt][2], a[mt][3],
                      sA + mt * 16 * 144 + ks * 32);
            uint32_t bq[8][2];
#pragma unroll
            for (int ntp = 0; ntp < 4; ntp++)
                LDSM4(bq[ntp * 2][0], bq[ntp * 2][1],
                      bq[ntp * 2 + 1][0], bq[ntp * 2 + 1][1],
                      sB + ntp * 16 * 144 + ks * 32);
#pragma unroll
            for (int mt = 0; mt < 2; mt++)
#pragma unroll
                for (int nt = 0; nt < 8; nt++)
                    MMAF16(acc[mt][nt], a[mt][0], a[mt][1], a[mt][2],
                           a[mt][3], bq[nt][0], bq[nt][1]);
        }
    }

    // ---- epilogue: bias + tanh + V-dot, reduce to per-row partials ----
    __syncthreads();
    const int t4 = lane & 3;
    float part[2][2];
#pragma unroll
    for (int mt = 0; mt < 2; mt++) { part[mt][0] = 0.f; part[mt][1] = 0.f; }
#pragma unroll
    for (int mt = 0; mt < 2; mt++)
#pragma unroll
        for (int nt = 0; nt < 8; nt++) {
            int n0 = wn * 64 + nt * 8 + 2 * t4;
            float v0 = Vs[n0], v1 = Vs[n0 + 1];
            float g0 = gBs[n0], g1 = gBs[n0 + 1];
            part[mt][0] += tanh_fast(acc[mt][nt][0] + g0) * v0 +
                           tanh_fast(acc[mt][nt][1] + g1) * v1;
            part[mt][1] += tanh_fast(acc[mt][nt][2] + g0) * v0 +
                           tanh_fast(acc[mt][nt][3] + g1) * v1;
        }
#pragma unroll
    for (int mt = 0; mt < 2; mt++)
#pragma unroll
        for (int rr = 0; rr < 2; rr++) {
            part[mt][rr] += __shfl_xor_sync(0xffffffffu, part[mt][rr], 1);
            part[mt][rr] += __shfl_xor_sync(0xffffffffu, part[mt][rr], 2);
        }
    if (t4 == 0) {
        int g = lane >> 2;
#pragma unroll
        for (int mt = 0; mt < 2; mt++)
#pragma unroll
            for (int rr = 0; rr < 2; rr++) {
                int row = wm * 32 + mt * 16 + rr * 8 + g;
                sPart[row * 4 + wn] = part[mt][rr];
            }
    }
    __syncthreads();
    if (tid < 64) {
        float s = sPart[tid * 4] + sPart[tid * 4 + 1] + sPart[tid * 4 + 2] +
                  sPart[tid * 4 + 3];
        atomicAdd(&g_scores[b * SS + s0 + tid], s);
    }
}

// ---------------------------------------------------------------------------
// kernC: softmax over S; writes attn; zeroes context region
// ---------------------------------------------------------------------------
__global__ __launch_bounds__(256) void kernC(float* __restrict__ out) {
    __shared__ float red[256];
    int b = blockIdx.x, tid = threadIdx.x;
    float v[8];
    float mx = -1e30f;
#pragma unroll
    for (int j = 0; j < 8; j++) {
        v[j] = g_scores[b * SS + tid + j * 256];
        mx = fmaxf(mx, v[j]);
    }
    red[tid] = mx;
    __syncthreads();
    for (int o = 128; o > 0; o >>= 1) {
        if (tid < o) red[tid] = fmaxf(red[tid], red[tid + o]);
        __syncthreads();
    }
    mx = red[0];
    __syncthreads();
    float s = 0.0f;
#pragma unroll
    for (int j = 0; j < 8; j++) {
        v[j] = __expf(v[j] - mx);
        s += v[j];
    }
    red[tid] = s;
    __syncthreads();
    for (int o = 128; o > 0; o >>= 1) {
        if (tid < o) red[tid] += red[tid + o];
        __syncthreads();
    }
    float inv = 1.0f / red[0];
#pragma unroll
    for (int j = 0; j < 8; j++)
        out[BB * UU + b * SS + tid + j * 256] = v[j] * inv;
    for (int i = tid; i < 512; i += 256) out[b * 512 + i] = 0.0f;
}

// ---------------------------------------------------------------------------
// kernD: context[b,d] = sum_s attn[b,s] * enc[b,s,d]
// ---------------------------------------------------------------------------
__global__ __launch_bounds__(512) void kernD(const float* __restrict__ enc,
                                             float* __restrict__ out) {
    __shared__ float as[128];
    int b = blockIdx.y, c = blockIdx.x, tid = threadIdx.x;
    if (tid < 128) as[tid] = out[BB * UU + b * SS + c * 128 + tid];
    __syncthreads();
    const float* e = enc + ((size_t)(b * SS + c * 128)) * DD + tid;
    float acc = 0.0f;
#pragma unroll 8
    for (int i = 0; i < 128; i++) acc = fmaf(as[i], e[(size_t)i * DD], acc);
    atomicAdd(&out[b * 512 + tid], acc);
}

// ---------------------------------------------------------------------------
extern "C" void kernel_launch(void* const* d_in, const int* in_sizes, int n_in,
                              void* d_out, int out_size) {
    const float* enc = (const float*)d_in[0];
    const float* dec = (const float*)d_in[1];
    const float* W1  = (const float*)d_in[2];
    const float* b1  = (const float*)d_in[3];
    const float* W2  = (const float*)d_in[4];
    const float* b2  = (const float*)d_in[5];
    const float* V   = (const float*)d_in[6];
    float* out = (float*)d_out;

    cudaFuncSetAttribute(kernB, cudaFuncAttributeMaxDynamicSharedMemorySize,
                         SMEM_B_TOTAL);

    kernE<<<65536, 256>>>(enc);
    kernW<<<1024, 256>>>(W1);
    kernA<<<BB, 512>>>(dec, W2, b1, b2);
    kernB<<<dim3(2048, 2), 256, SMEM_B_TOTAL>>>(V);
    kernC<<<BB, 256>>>(out);
    kernD<<<dim3(16, BB), 512>>>(enc, out);
}

// round 13
// speedup vs baseline: 2.2014x; 1.4905x over previous
#include <cuda_runtime.h>
#include <cuda_fp16.h>
#include <cstdint>

#define BB 64
#define SS 2048
#define DD 512
#define UU 512

// ---------------- scratch globals (no allocations allowed) ------------------
__device__ float g_bias[BB * UU];                  // dec@W2 + b1 + b2
__device__ float g_scores[BB * SS];                // pre-softmax scores
__device__ __half g_encH[(size_t)BB * SS * DD];    // enc as fp16 (128 MB)
__device__ __half g_W1h[(size_t)UU * DD];          // W1 as [u][k] fp16

// ---------------- helpers ----------------------------------------------------
__device__ __forceinline__ float tanh_fast(float x) {
    float e = __expf(2.0f * x);
    return 1.0f - __fdividef(2.0f, e + 1.0f);
}
__device__ __forceinline__ uint32_t smem_u32(const void* p) {
    uint32_t a;
    asm("{ .reg .u64 t; cvta.to.shared.u64 t, %1; cvt.u32.u64 %0, t; }"
        : "=r"(a) : "l"(p));
    return a;
}
#define CP16(dst, src) \
    asm volatile("cp.async.cg.shared.global [%0], [%1], 16;" \
                 :: "r"(dst), "l"(src) : "memory")
#define LDSM4(r0, r1, r2, r3, addr) \
    asm volatile("ldmatrix.sync.aligned.m8n8.x4.shared.b16 {%0,%1,%2,%3}, [%4];" \
                 : "=r"(r0), "=r"(r1), "=r"(r2), "=r"(r3) : "r"(addr))
#define MMAF16(d, a0, a1, a2, a3, b0, b1) \
    asm volatile( \
        "mma.sync.aligned.m16n8k16.row.col.f32.f16.f16.f32 " \
        "{%0,%1,%2,%3}, {%4,%5,%6,%7}, {%8,%9}, {%0,%1,%2,%3};" \
        : "+f"(d[0]), "+f"(d[1]), "+f"(d[2]), "+f"(d[3]) \
        : "r"(a0), "r"(a1), "r"(a2), "r"(a3), "r"(b0), "r"(b1))

// ---------------------------------------------------------------------------
// kernEWA: fused prep. Blocks [0,32768): enc fp32->fp16 (8 elems/thread).
// Blocks [32768,33792): W1 transpose->fp16 + zero g_scores.
// Blocks [33792,33920): g_bias = dec@W2 + b1 + b2.
// ---------------------------------------------------------------------------
#define E_BLKS 32768
#define W_BLKS 1024
#define A_BLKS 128

__global__ __launch_bounds__(256) void kernEWA(const float* __restrict__ enc,
                                               const float* __restrict__ W1,
                                               const float* __restrict__ dec,
                                               const float* __restrict__ W2,
                                               const float* __restrict__ b1,
                                               const float* __restrict__ b2) {
    int blk = blockIdx.x;
    int tid = threadIdx.x;
    if (blk < E_BLKS) {
        size_t lin = (size_t)blk * 256 + tid;         // 8.39M threads x 8 elems
        const float4* src = (const float4*)enc + lin * 2;
        float4 f0 = src[0], f1 = src[1];
        __half2 p0 = __floats2half2_rn(f0.x, f0.y);
        __half2 p1 = __floats2half2_rn(f0.z, f0.w);
        __half2 p2 = __floats2half2_rn(f1.x, f1.y);
        __half2 p3 = __floats2half2_rn(f1.z, f1.w);
        uint4 v;
        v.x = *(uint32_t*)&p0; v.y = *(uint32_t*)&p1;
        v.z = *(uint32_t*)&p2; v.w = *(uint32_t*)&p3;
        *((uint4*)g_encH + lin) = v;
    } else if (blk < E_BLKS + W_BLKS) {
        int idx = (blk - E_BLKS) * 256 + tid;          // 0..262143
        int u = idx & 511, kg = idx >> 9;
        g_W1h[(size_t)u * DD + kg] = __float2half_rn(W1[(size_t)kg * UU + u]);
        if (idx < BB * SS) g_scores[idx] = 0.0f;
    } else {
        __shared__ float ds[DD];
        int ab = blk - E_BLKS - W_BLKS;                // 0..127
        int b = ab >> 1, half = ab & 1;
        ds[tid] = dec[b * DD + tid];
        ds[tid + 256] = dec[b * DD + tid + 256];
        __syncthreads();
        int u = half * 256 + tid;
        float acc = 0.0f;
#pragma unroll 8
        for (int k = 0; k < DD; k++) acc = fmaf(ds[k], W2[k * UU + u], acc);
        g_bias[b * UU + u] = acc + b1[u] + b2[u];
    }
}

// ---------------------------------------------------------------------------
// kernB: fp16 single-pass mma.sync GEMM, tile M64 x N256 per CTA, K=512.
// 8 k64 tiles, 2-stage cp.async ring, one __syncthreads per tile, 2 CTAs/SM.
// Row stride 144 B (128 B data + 16 pad).
// ---------------------------------------------------------------------------
#define ASLOT 9216              // 64 rows * 144 B
#define SLOT  46080             // A (9216) + B (36864)
#define EXTRA 92160             // 2 stages
#define SMEM_B_TOTAL (EXTRA + 1024 + 1024 + 1024)

__global__ __launch_bounds__(256, 2) void kernB(const float* __restrict__ Vp) {
    extern __shared__ char smraw[];
    const uint32_t smem = smem_u32(smraw);
    float* gBs = (float*)(smraw + EXTRA);
    float* Vs = (float*)(smraw + EXTRA + 1024);
    float* sPart = (float*)(smraw + EXTRA + 2048);

    const int tid = threadIdx.x;
    const int lane = tid & 31, w = tid >> 5;
    const int wm = w & 1, wn = w >> 1;          // warp tile 32(M) x 64(N)
    const int R = blockIdx.x * 64;
    const int b = blockIdx.x >> 5;
    const int s0 = (blockIdx.x & 31) * 64;
    const int N0 = blockIdx.y * 256;

    {
        gBs[tid] = g_bias[b * 512 + N0 + tid];
        Vs[tid] = Vp[N0 + tid];
    }

    // tile it (0..7): k0 = it*64 fp16 elements = it*128 bytes
    auto issue_tile = [&](int it, int slot) {
        const char* aSrc = (const char*)g_encH + (size_t)R * 1024 + it * 128;
        const char* bSrc = (const char*)g_W1h + (size_t)N0 * 1024 + it * 128;
        uint32_t aDst = smem + slot * SLOT;
        uint32_t bDst = aDst + ASLOT;
#pragma unroll
        for (int i = 0; i < 2; i++) {
            int lin = tid + i * 256;
            int r = lin >> 3, c = lin & 7;
            CP16(aDst + r * 144 + c * 16, aSrc + (size_t)r * 1024 + c * 16);
        }
#pragma unroll
        for (int i = 0; i < 8; i++) {
            int lin = tid + i * 256;
            int r = lin >> 3, c = lin & 7;
            CP16(bDst + r * 144 + c * 16, bSrc + (size_t)r * 1024 + c * 16);
        }
        asm volatile("cp.async.commit_group;" ::: "memory");
    };

    float acc[2][8][4];
#pragma unroll
    for (int mt = 0; mt < 2; mt++)
#pragma unroll
        for (int nt = 0; nt < 8; nt++)
#pragma unroll
            for (int j = 0; j < 4; j++) acc[mt][nt][j] = 0.0f;

    issue_tile(0, 0);

    const uint32_t aRowOff =
        (uint32_t)((wm * 32 + (lane & 15)) * 144 + ((lane >> 4) & 1) * 16);
    const uint32_t bRowOff =
        (uint32_t)((wn * 64 + (lane & 7) + ((lane >> 4) & 1) * 8) * 144 +
                   ((lane >> 3) & 1) * 16);

    for (int it = 0; it < 8; it++) {
        asm volatile("cp.async.wait_group 0;" ::: "memory");
        __syncthreads();
        if (it + 1 < 8) issue_tile(it + 1, (it + 1) & 1);

        const uint32_t sbase = smem + (it & 1) * SLOT;
        const uint32_t sA = sbase + aRowOff;
        const uint32_t sB = sbase + ASLOT + bRowOff;
#pragma unroll
        for (int ks = 0; ks < 4; ks++) {
            uint32_t a[2][4];
#pragma unroll
            for (int mt = 0; mt < 2; mt++)
                LDSM4(a[mt][0], a[mt][1], a[mt][2], a[mt][3],
                      sA + mt * 16 * 144 + ks * 32);
            uint32_t bq[8][2];
#pragma unroll
            for (int ntp = 0; ntp < 4; ntp++)
                LDSM4(bq[ntp * 2][0], bq[ntp * 2][1],
                      bq[ntp * 2 + 1][0], bq[ntp * 2 + 1][1],
                      sB + ntp * 16 * 144 + ks * 32);
#pragma unroll
            for (int mt = 0; mt < 2; mt++)
#pragma unroll
                for (int nt = 0; nt < 8; nt++)
                    MMAF16(acc[mt][nt], a[mt][0], a[mt][1], a[mt][2],
                           a[mt][3], bq[nt][0], bq[nt][1]);
        }
    }

    // ---- epilogue: bias + tanh + V-dot, reduce to per-row partials ----
    __syncthreads();
    const int t4 = lane & 3;
    float part[2][2];
#pragma unroll
    for (int mt = 0; mt < 2; mt++) { part[mt][0] = 0.f; part[mt][1] = 0.f; }
#pragma unroll
    for (int mt = 0; mt < 2; mt++)
#pragma unroll
        for (int nt = 0; nt < 8; nt++) {
            int n0 = wn * 64 + nt * 8 + 2 * t4;
            float v0 = Vs[n0], v1 = Vs[n0 + 1];
            float g0 = gBs[n0], g1 = gBs[n0 + 1];
            part[mt][0] += tanh_fast(acc[mt][nt][0] + g0) * v0 +
                           tanh_fast(acc[mt][nt][1] + g1) * v1;
            part[mt][1] += tanh_fast(acc[mt][nt][2] + g0) * v0 +
                           tanh_fast(acc[mt][nt][3] + g1) * v1;
        }
#pragma unroll
    for (int mt = 0; mt < 2; mt++)
#pragma unroll
        for (int rr = 0; rr < 2; rr++) {
            part[mt][rr] += __shfl_xor_sync(0xffffffffu, part[mt][rr], 1);
            part[mt][rr] += __shfl_xor_sync(0xffffffffu, part[mt][rr], 2);
        }
    if (t4 == 0) {
        int g = lane >> 2;
#pragma unroll
        for (int mt = 0; mt < 2; mt++)
#pragma unroll
            for (int rr = 0; rr < 2; rr++) {
                int row = wm * 32 + mt * 16 + rr * 8 + g;
                sPart[row * 4 + wn] = part[mt][rr];
            }
    }
    __syncthreads();
    if (tid < 64) {
        float s = sPart[tid * 4] + sPart[tid * 4 + 1] + sPart[tid * 4 + 2] +
                  sPart[tid * 4 + 3];
        atomicAdd(&g_scores[b * SS + s0 + tid], s);
    }
}

// ---------------------------------------------------------------------------
// kernC: softmax over S; writes attn; zeroes context region
// ---------------------------------------------------------------------------
__global__ __launch_bounds__(256) void kernC(float* __restrict__ out) {
    __shared__ float red[256];
    int b = blockIdx.x, tid = threadIdx.x;
    float v[8];
    float mx = -1e30f;
#pragma unroll
    for (int j = 0; j < 8; j++) {
        v[j] = g_scores[b * SS + tid + j * 256];
        mx = fmaxf(mx, v[j]);
    }
    red[tid] = mx;
    __syncthreads();
    for (int o = 128; o > 0; o >>= 1) {
        if (tid < o) red[tid] = fmaxf(red[tid], red[tid + o]);
        __syncthreads();
    }
    mx = red[0];
    __syncthreads();
    float s = 0.0f;
#pragma unroll
    for (int j = 0; j < 8; j++) {
        v[j] = __expf(v[j] - mx);
        s += v[j];
    }
    red[tid] = s;
    __syncthreads();
    for (int o = 128; o > 0; o >>= 1) {
        if (tid < o) red[tid] += red[tid + o];
        __syncthreads();
    }
    float inv = 1.0f / red[0];
#pragma unroll
    for (int j = 0; j < 8; j++)
        out[BB * UU + b * SS + tid + j * 256] = v[j] * inv;
    for (int i = tid; i < 512; i += 256) out[b * 512 + i] = 0.0f;
}

// ---------------------------------------------------------------------------
// kernD: context[b,d] = sum_s attn[b,s] * encH[b,s,d]  (fp16 enc image)
// ---------------------------------------------------------------------------
__global__ __launch_bounds__(512) void kernD(float* __restrict__ out) {
    __shared__ float as[128];
    int b = blockIdx.y, c = blockIdx.x, tid = threadIdx.x;
    if (tid < 128) as[tid] = out[BB * UU + b * SS + c * 128 + tid];
    __syncthreads();
    const __half* e = g_encH + ((size_t)(b * SS + c * 128)) * DD + tid;
    float acc = 0.0f;
#pragma unroll 8
    for (int i = 0; i < 128; i++)
        acc = fmaf(as[i], __half2float(e[(size_t)i * DD]), acc);
    atomicAdd(&out[b * 512 + tid], acc);
}

// ---------------------------------------------------------------------------
extern "C" void kernel_launch(void* const* d_in, const int* in_sizes, int n_in,
                              void* d_out, int out_size) {
    const float* enc = (const float*)d_in[0];
    const float* dec = (const float*)d_in[1];
    const float* W1  = (const float*)d_in[2];
    const float* b1  = (const float*)d_in[3];
    const float* W2  = (const float*)d_in[4];
    const float* b2  = (const float*)d_in[5];
    const float* V   = (const float*)d_in[6];
    float* out = (float*)d_out;

    cudaFuncSetAttribute(kernB, cudaFuncAttributeMaxDynamicSharedMemorySize,
                         SMEM_B_TOTAL);

    kernEWA<<<E_BLKS + W_BLKS + A_BLKS, 256>>>(enc, W1, dec, W2, b1, b2);
    kernB<<<dim3(2048, 2), 256, SMEM_B_TOTAL>>>(V);
    kernC<<<BB, 256>>>(out);
    kernD<<<dim3(16, BB), 512>>>(out);
}

// round 15
// speedup vs baseline: 2.2454x; 1.0200x over previous
#include <cuda_runtime.h>
#include <cuda_fp16.h>
#include <cstdint>

#define BB 64
#define SS 2048
#define DD 512
#define UU 512

// ---------------- scratch globals (no allocations allowed) ------------------
__device__ float g_bias[BB * UU];                  // dec@W2 + b1 + b2
__device__ float g_scores[BB * SS];                // pre-softmax scores
__device__ __half g_encH[(size_t)BB * SS * DD];    // enc as fp16 (128 MB)
__device__ __half g_W1h[(size_t)UU * DD];          // W1 as [u][k] fp16

// ---------------- helpers ----------------------------------------------------
__device__ __forceinline__ float tanh_fast(float x) {
    float e = __expf(2.0f * x);
    return 1.0f - __fdividef(2.0f, e + 1.0f);
}
__device__ __forceinline__ uint32_t smem_u32(const void* p) {
    uint32_t a;
    asm("{ .reg .u64 t; cvta.to.shared.u64 t, %1; cvt.u32.u64 %0, t; }"
        : "=r"(a) : "l"(p));
    return a;
}
#define CP16(dst, src) \
    asm volatile("cp.async.cg.shared.global [%0], [%1], 16;" \
                 :: "r"(dst), "l"(src) : "memory")
#define LDSM4(r0, r1, r2, r3, addr) \
    asm volatile("ldmatrix.sync.aligned.m8n8.x4.shared.b16 {%0,%1,%2,%3}, [%4];" \
                 : "=r"(r0), "=r"(r1), "=r"(r2), "=r"(r3) : "r"(addr))
#define MMAF16(d, a0, a1, a2, a3, b0, b1) \
    asm volatile( \
        "mma.sync.aligned.m16n8k16.row.col.f32.f16.f16.f32 " \
        "{%0,%1,%2,%3}, {%4,%5,%6,%7}, {%8,%9}, {%0,%1,%2,%3};" \
        : "+f"(d[0]), "+f"(d[1]), "+f"(d[2]), "+f"(d[3]) \
        : "r"(a0), "r"(a1), "r"(a2), "r"(a3), "r"(b0), "r"(b1))

// ---------------------------------------------------------------------------
// kernEWA: fused prep. Blocks [0,32768): enc fp32->fp16 (8 elems/thread).
// Blocks [32768,33792): W1 transpose->fp16 + zero g_scores.
// Blocks [33792,33920): g_bias = dec@W2 + b1 + b2.
// ---------------------------------------------------------------------------
#define E_BLKS 32768
#define W_BLKS 1024
#define A_BLKS 128

__global__ __launch_bounds__(256) void kernEWA(const float* __restrict__ enc,
                                               const float* __restrict__ W1,
                                               const float* __restrict__ dec,
                                               const float* __restrict__ W2,
                                               const float* __restrict__ b1,
                                               const float* __restrict__ b2) {
    int blk = blockIdx.x;
    int tid = threadIdx.x;
    if (blk < E_BLKS) {
        size_t lin = (size_t)blk * 256 + tid;
        const float4* src = (const float4*)enc + lin * 2;
        float4 f0 = src[0], f1 = src[1];
        __half2 p0 = __floats2half2_rn(f0.x, f0.y);
        __half2 p1 = __floats2half2_rn(f0.z, f0.w);
        __half2 p2 = __floats2half2_rn(f1.x, f1.y);
        __half2 p3 = __floats2half2_rn(f1.z, f1.w);
        uint4 v;
        v.x = *(uint32_t*)&p0; v.y = *(uint32_t*)&p1;
        v.z = *(uint32_t*)&p2; v.w = *(uint32_t*)&p3;
        *((uint4*)g_encH + lin) = v;
    } else if (blk < E_BLKS + W_BLKS) {
        int idx = (blk - E_BLKS) * 256 + tid;
        int u = idx & 511, kg = idx >> 9;
        g_W1h[(size_t)u * DD + kg] = __float2half_rn(W1[(size_t)kg * UU + u]);
        if (idx < BB * SS) g_scores[idx] = 0.0f;
    } else {
        __shared__ float ds[DD];
        int ab = blk - E_BLKS - W_BLKS;
        int b = ab >> 1, half = ab & 1;
        ds[tid] = dec[b * DD + tid];
        ds[tid + 256] = dec[b * DD + tid + 256];
        __syncthreads();
        int u = half * 256 + tid;
        float acc = 0.0f;
#pragma unroll 8
        for (int k = 0; k < DD; k++) acc = fmaf(ds[k], W2[k * UU + u], acc);
        g_bias[b * UU + u] = acc + b1[u] + b2[u];
    }
}

// ---------------------------------------------------------------------------
// kernB: fp16 single-pass mma.sync GEMM, tile M64 x N256 per CTA, K=512.
// 8 k64 tiles, 2-stage cp.async ring, one __syncthreads per tile, 2 CTAs/SM.
// ---------------------------------------------------------------------------
#define ASLOT 9216              // 64 rows * 144 B
#define SLOT  46080             // A (9216) + B (36864)
#define EXTRA 92160             // 2 stages
#define SMEM_B_TOTAL (EXTRA + 1024 + 1024 + 1024)

__global__ __launch_bounds__(256, 2) void kernB(const float* __restrict__ Vp) {
    extern __shared__ char smraw[];
    const uint32_t smem = smem_u32(smraw);
    float* gBs = (float*)(smraw + EXTRA);
    float* Vs = (float*)(smraw + EXTRA + 1024);
    float* sPart = (float*)(smraw + EXTRA + 2048);

    const int tid = threadIdx.x;
    const int lane = tid & 31, w = tid >> 5;
    const int wm = w & 1, wn = w >> 1;
    const int R = blockIdx.x * 64;
    const int b = blockIdx.x >> 5;
    const int s0 = (blockIdx.x & 31) * 64;
    const int N0 = blockIdx.y * 256;

    {
        gBs[tid] = g_bias[b * 512 + N0 + tid];
        Vs[tid] = Vp[N0 + tid];
    }

    auto issue_tile = [&](int it, int slot) {
        const char* aSrc = (const char*)g_encH + (size_t)R * 1024 + it * 128;
        const char* bSrc = (const char*)g_W1h + (size_t)N0 * 1024 + it * 128;
        uint32_t aDst = smem + slot * SLOT;
        uint32_t bDst = aDst + ASLOT;
#pragma unroll
        for (int i = 0; i < 2; i++) {
            int lin = tid + i * 256;
            int r = lin >> 3, c = lin & 7;
            CP16(aDst + r * 144 + c * 16, aSrc + (size_t)r * 1024 + c * 16);
        }
#pragma unroll
        for (int i = 0; i < 8; i++) {
            int lin = tid + i * 256;
            int r = lin >> 3, c = lin & 7;
            CP16(bDst + r * 144 + c * 16, bSrc + (size_t)r * 1024 + c * 16);
        }
        asm volatile("cp.async.commit_group;" ::: "memory");
    };

    float acc[2][8][4];
#pragma unroll
    for (int mt = 0; mt < 2; mt++)
#pragma unroll
        for (int nt = 0; nt < 8; nt++)
#pragma unroll
            for (int j = 0; j < 4; j++) acc[mt][nt][j] = 0.0f;

    issue_tile(0, 0);

    const uint32_t aRowOff =
        (uint32_t)((wm * 32 + (lane & 15)) * 144 + ((lane >> 4) & 1) * 16);
    const uint32_t bRowOff =
        (uint32_t)((wn * 64 + (lane & 7) + ((lane >> 4) & 1) * 8) * 144 +
                   ((lane >> 3) & 1) * 16);

    for (int it = 0; it < 8; it++) {
        asm volatile("cp.async.wait_group 0;" ::: "memory");
        __syncthreads();
        if (it + 1 < 8) issue_tile(it + 1, (it + 1) & 1);

        const uint32_t sbase = smem + (it & 1) * SLOT;
        const uint32_t sA = sbase + aRowOff;
        const uint32_t sB = sbase + ASLOT + bRowOff;
#pragma unroll
        for (int ks = 0; ks < 4; ks++) {
            uint32_t a[2][4];
#pragma unroll
            for (int mt = 0; mt < 2; mt++)
                LDSM4(a[mt][0], a[mt][1], a[mt][2], a[mt][3],
                      sA + mt * 16 * 144 + ks * 32);
            uint32_t bq[8][2];
#pragma unroll
            for (int ntp = 0; ntp < 4; ntp++)
                LDSM4(bq[ntp * 2][0], bq[ntp * 2][1],
                      bq[ntp * 2 + 1][0], bq[ntp * 2 + 1][1],
                      sB + ntp * 16 * 144 + ks * 32);
#pragma unroll
            for (int mt = 0; mt < 2; mt++)
#pragma unroll
                for (int nt = 0; nt < 8; nt++)
                    MMAF16(acc[mt][nt], a[mt][0], a[mt][1], a[mt][2],
                           a[mt][3], bq[nt][0], bq[nt][1]);
        }
    }

    // ---- epilogue: bias + tanh + V-dot, reduce to per-row partials ----
    __syncthreads();
    const int t4 = lane & 3;
    float part[2][2];
#pragma unroll
    for (int mt = 0; mt < 2; mt++) { part[mt][0] = 0.f; part[mt][1] = 0.f; }
#pragma unroll
    for (int mt = 0; mt < 2; mt++)
#pragma unroll
        for (int nt = 0; nt < 8; nt++) {
            int n0 = wn * 64 + nt * 8 + 2 * t4;
            float v0 = Vs[n0], v1 = Vs[n0 + 1];
            float g0 = gBs[n0], g1 = gBs[n0 + 1];
            part[mt][0] += tanh_fast(acc[mt][nt][0] + g0) * v0 +
                           tanh_fast(acc[mt][nt][1] + g1) * v1;
            part[mt][1] += tanh_fast(acc[mt][nt][2] + g0) * v0 +
                           tanh_fast(acc[mt][nt][3] + g1) * v1;
        }
#pragma unroll
    for (int mt = 0; mt < 2; mt++)
#pragma unroll
        for (int rr = 0; rr < 2; rr++) {
            part[mt][rr] += __shfl_xor_sync(0xffffffffu, part[mt][rr], 1);
            part[mt][rr] += __shfl_xor_sync(0xffffffffu, part[mt][rr], 2);
        }
    if (t4 == 0) {
        int g = lane >> 2;
#pragma unroll
        for (int mt = 0; mt < 2; mt++)
#pragma unroll
            for (int rr = 0; rr < 2; rr++) {
                int row = wm * 32 + mt * 16 + rr * 8 + g;
                sPart[row * 4 + wn] = part[mt][rr];
            }
    }
    __syncthreads();
    if (tid < 64) {
        float s = sPart[tid * 4] + sPart[tid * 4 + 1] + sPart[tid * 4 + 2] +
                  sPart[tid * 4 + 3];
        atomicAdd(&g_scores[b * SS + s0 + tid], s);
    }
}

// ---------------------------------------------------------------------------
// kernC: softmax over S; writes attn; zeroes context region
// ---------------------------------------------------------------------------
__global__ __launch_bounds__(256) void kernC(float* __restrict__ out) {
    __shared__ float red[256];
    int b = blockIdx.x, tid = threadIdx.x;
    float v[8];
    float mx = -1e30f;
#pragma unroll
    for (int j = 0; j < 8; j++) {
        v[j] = g_scores[b * SS + tid + j * 256];
        mx = fmaxf(mx, v[j]);
    }
    red[tid] = mx;
    __syncthreads();
    for (int o = 128; o > 0; o >>= 1) {
        if (tid < o) red[tid] = fmaxf(red[tid], red[tid + o]);
        __syncthreads();
    }
    mx = red[0];
    __syncthreads();
    float s = 0.0f;
#pragma unroll
    for (int j = 0; j < 8; j++) {
        v[j] = __expf(v[j] - mx);
        s += v[j];
    }
    red[tid] = s;
    __syncthreads();
    for (int o = 128; o > 0; o >>= 1) {
        if (tid < o) red[tid] += red[tid + o];
        __syncthreads();
    }
    float inv = 1.0f / red[0];
#pragma unroll
    for (int j = 0; j < 8; j++)
        out[BB * UU + b * SS + tid + j * 256] = v[j] * inv;
    for (int i = tid; i < 512; i += 256) out[b * 512 + i] = 0.0f;
}

// ---------------------------------------------------------------------------
// kernD: context[b,d] = sum_s attn[b,s] * encH[b,s,d]  (fp16 enc image)
// 4 groups of 128 threads; each thread loads uint2 (4 halves) per row ->
// 256 B/warp/LDG; smem cross-group reduction; one atomicAdd per d.
// ---------------------------------------------------------------------------
__global__ __launch_bounds__(512) void kernD(float* __restrict__ out) {
    __shared__ float as[128];
    __shared__ float red[4 * 512];
    int b = blockIdx.y, c = blockIdx.x, tid = threadIdx.x;
    if (tid < 128) as[tid] = out[BB * UU + b * SS + c * 128 + tid];
    __syncthreads();
    const int grp = tid >> 7;          // 0..3
    const int lc = tid & 127;          // 0..127
    const int d0 = lc * 4;
    const __half* e = g_encH + ((size_t)(b * SS + c * 128)) * DD + d0;
    float a0 = 0.f, a1 = 0.f, a2 = 0.f, a3 = 0.f;
#pragma unroll 8
    for (int i = grp; i < 128; i += 4) {
        float wgt = as[i];
        uint2 v = *(const uint2*)(e + (size_t)i * DD);
        __half2 h0 = *(__half2*)&v.x, h1 = *(__half2*)&v.y;
        float2 f0 = __half22float2(h0), f1 = __half22float2(h1);
        a0 = fmaf(wgt, f0.x, a0);
        a1 = fmaf(wgt, f0.y, a1);
        a2 = fmaf(wgt, f1.x, a2);
        a3 = fmaf(wgt, f1.y, a3);
    }
    float4 st = {a0, a1, a2, a3};
    *(float4*)(&red[grp * 512 + d0]) = st;
    __syncthreads();
    float s = red[tid] + red[512 + tid] + red[1024 + tid] + red[1536 + tid];
    atomicAdd(&out[b * 512 + tid], s);
}

// ---------------------------------------------------------------------------
extern "C" void kernel_launch(void* const* d_in, const int* in_sizes, int n_in,
                              void* d_out, int out_size) {
    const float* enc = (const float*)d_in[0];
    const float* dec = (const float*)d_in[1];
    const float* W1  = (const float*)d_in[2];
    const float* b1  = (const float*)d_in[3];
    const float* W2  = (const float*)d_in[4];
    const float* b2  = (const float*)d_in[5];
    const float* V   = (const float*)d_in[6];
    float* out = (float*)d_out;

    cudaFuncSetAttribute(kernB, cudaFuncAttributeMaxDynamicSharedMemorySize,
                         SMEM_B_TOTAL);

    kernEWA<<<E_BLKS + W_BLKS + A_BLKS, 256>>>(enc, W1, dec, W2, b1, b2);
    kernB<<<dim3(2048, 2), 256, SMEM_B_TOTAL>>>(V);
    kernC<<<BB, 256>>>(out);
    kernD<<<dim3(16, BB), 512>>>(out);
}